// round 15
// baseline (speedup 1.0000x reference)
#include <cuda_runtime.h>
#include <math.h>

#define N_NODES 100000
#define N_EDGES 1600000
#define F_INDIM 128
#define AGG 48
#define FC_H 192
#define NC 10
#define SLOPE 0.2f

// ---------------- scratch (static device globals; no allocation) ----------------
__device__ float  d_xl[N_NODES * AGG];
__device__ float  d_xr[N_NODES * AGG];
__device__ float  d_h [N_NODES * AGG];
__device__ float  d_g [AGG];
__device__ int    d_deg[N_NODES];
__device__ int    d_off[N_NODES + 1];
__device__ int    d_cur[N_NODES];
__device__ int    d_ctr[4];            // per-layer work-stealing counters
__device__ int    d_srcs[N_EDGES];     // src ids, CSR (dst-sorted) order
__device__ float4 d_eas[N_EDGES];      // edge attrs, CSR order

// Fixed-point warp-group add-reduction via redux.sync.add.s32 (sm_80+, valid on sm_100).
// Per-lane partials are O(+-5); 2^20 scaling keeps 16-lane sums < 2^27 and adds
// <= 1e-5 absolute logit error -> negligible vs the 1e-3 rel-err gate.
__device__ __forceinline__ float redux_add_fix(float v, unsigned mask) {
    int i = __float2int_rn(v * 1048576.f);
    int r;
    asm volatile("redux.sync.add.s32 %0, %1, %2;" : "=r"(r) : "r"(i), "r"(mask));
    return (float)r * (1.f / 1048576.f);
}

// ---------------- CSR build ----------------
__global__ void k_zero() {
    int i = blockIdx.x * blockDim.x + threadIdx.x;
    if (i < N_NODES) d_deg[i] = 0;
    if (i < AGG)     d_g[i] = 0.f;
    if (i < 4)       d_ctr[i] = 0;
}

__global__ void k_count(const int* __restrict__ dst) {
    int e = blockIdx.x * blockDim.x + threadIdx.x;
    if (e < N_EDGES) atomicAdd(&d_deg[dst[e]], 1);
}

// single-block exclusive scan, int4-vectorized (25 chunk iterations)
__global__ void k_scan() {
    __shared__ int wsum[32];
    __shared__ int carry;
    int t = threadIdx.x, lane = t & 31, w = t >> 5;
    if (t == 0) carry = 0;
    __syncthreads();
    for (int base = 0; base < N_NODES; base += 4096) {
        int idx = base + t * 4;
        int4 v4 = make_int4(0, 0, 0, 0);
        if (idx < N_NODES) v4 = *(const int4*)&d_deg[idx];   // N_NODES % 4 == 0
        int s = v4.x + v4.y + v4.z + v4.w;
        int x = s;
        #pragma unroll
        for (int o = 1; o < 32; o <<= 1) {
            int y = __shfl_up_sync(0xffffffffu, x, o);
            if (lane >= o) x += y;
        }
        if (lane == 31) wsum[w] = x;
        __syncthreads();
        if (w == 0) {
            int ss = wsum[lane];
            #pragma unroll
            for (int o = 1; o < 32; o <<= 1) {
                int y = __shfl_up_sync(0xffffffffu, ss, o);
                if (lane >= o) ss += y;
            }
            wsum[lane] = ss;
        }
        __syncthreads();
        int incl = x + (w > 0 ? wsum[w - 1] : 0) + carry;
        if (idx < N_NODES) {
            int o0 = incl - s;
            int o1 = o0 + v4.x;
            int o2 = o1 + v4.y;
            int o3 = o2 + v4.z;
            d_off[idx] = o0;     d_cur[idx] = o0;
            d_off[idx + 1] = o1; d_cur[idx + 1] = o1;
            d_off[idx + 2] = o2; d_cur[idx + 2] = o2;
            d_off[idx + 3] = o3; d_cur[idx + 3] = o3;
        }
        __syncthreads();
        if (t == 1023) carry = incl;
        __syncthreads();
    }
    if (t == 0) d_off[N_NODES] = carry;
}

// scatter edges into CSR order, pre-gathering src id and edge attr
__global__ void k_scatter(const int* __restrict__ src, const int* __restrict__ dst,
                          const float4* __restrict__ ea) {
    int e = blockIdx.x * blockDim.x + threadIdx.x;
    if (e < N_EDGES) {
        int p = atomicAdd(&d_cur[dst[e]], 1);
        d_srcs[p] = src[e];
        d_eas[p]  = ea[e];
    }
}

// ---------------- fused node-wise linears: xl = h@Wl.T+bl, xr = h@Wr.T+br ----------------
// Register-tiled: thread = 4 nodes x 4 channels. 240 active threads = 80 nodes/block.
__global__ void k_gemm2(const float* __restrict__ hin_ext, int use_h, int D,
                        const float* __restrict__ Wl, const float* __restrict__ bl,
                        const float* __restrict__ Wr, const float* __restrict__ br) {
    __shared__ float WsL[F_INDIM * AGG];  // transposed: Ws[k*48 + c]
    __shared__ float WsR[F_INDIM * AGG];
    const float* hin = use_h ? d_h : hin_ext;

    int t = threadIdx.x;
    int tot = D * AGG;
    for (int j = t; j < tot; j += blockDim.x) {
        int c = j / D, k = j % D;          // W row-major [AGG][D]
        WsL[k * AGG + c] = Wl[j];
        WsR[k * AGG + c] = Wr[j];
    }
    __syncthreads();
    if (t >= 240) return;

    int cg = t % 12;
    int grp = t / 12;
    int n0 = blockIdx.x * 80 + grp * 4;

    float4 bL = ((const float4*)bl)[cg];
    float4 bR = ((const float4*)br)[cg];
    float4 aL[4] = {bL, bL, bL, bL};
    float4 aR[4] = {bR, bR, bR, bR};

    const float* hp = hin + (size_t)n0 * D;

    for (int k = 0; k < D; k += 4) {
        float4 h4[4];
        #pragma unroll
        for (int nn = 0; nn < 4; nn++)
            h4[nn] = *(const float4*)(hp + nn * D + k);
        #pragma unroll
        for (int j = 0; j < 4; j++) {
            float4 wl = *(const float4*)&WsL[(k + j) * AGG + cg * 4];
            float4 wr = *(const float4*)&WsR[(k + j) * AGG + cg * 4];
            #pragma unroll
            for (int nn = 0; nn < 4; nn++) {
                float hv = (j == 0) ? h4[nn].x : (j == 1) ? h4[nn].y
                         : (j == 2) ? h4[nn].z : h4[nn].w;
                aL[nn].x = fmaf(hv, wl.x, aL[nn].x);
                aL[nn].y = fmaf(hv, wl.y, aL[nn].y);
                aL[nn].z = fmaf(hv, wl.z, aL[nn].z);
                aL[nn].w = fmaf(hv, wl.w, aL[nn].w);
                aR[nn].x = fmaf(hv, wr.x, aR[nn].x);
                aR[nn].y = fmaf(hv, wr.y, aR[nn].y);
                aR[nn].z = fmaf(hv, wr.z, aR[nn].z);
                aR[nn].w = fmaf(hv, wr.w, aR[nn].w);
            }
        }
    }
    #pragma unroll
    for (int nn = 0; nn < 4; nn++) {
        ((float4*)d_xl)[(n0 + nn) * 12 + cg] = aL[nn];
        ((float4*)d_xr)[(n0 + nn) * 12 + cg] = aR[nn];
    }
}

// ---------------- GATv2 aggregation: work-stealing warps, halves split edges ----------------
// Each warp grabs batches of 8 nodes via atomicAdd (near-perfect load balance).
// No running max (den = sum exp, acc = sum exp*xl); 2-edge unroll; half-warp split.
// Logit reduction = ONE redux.sync.add.s32 (fixed-point) on the half mask instead of a
// 4-level shfl chain. Cross-half merge (pairwise exchange) stays shfl, after syncwarp.
__global__ void k_agg(const float* __restrict__ We, const float* __restrict__ att,
                      const float* __restrict__ bias, int layer, int fuse_readout) {
    __shared__ float sG[AGG];
    int t = threadIdx.x;
    if (t < AGG) sG[t] = 0.f;
    __syncthreads();

    int lane = t & 31;
    int half = lane >> 4, L = lane & 15;
    unsigned hmask = 0xFFFFu << (half * 16);
    bool active = (L < 12);
    float4 z = make_float4(0, 0, 0, 0);

    float4 a4 = active ? __ldg(((const float4*)att) + L)  : z;
    float4 b4 = active ? __ldg(((const float4*)bias) + L) : z;
    float4 W0, W1, W2, W3;
    if (active) {
        int c4 = L * 4;
        W0 = __ldg(((const float4*)We) + c4 + 0);
        W1 = __ldg(((const float4*)We) + c4 + 1);
        W2 = __ldg(((const float4*)We) + c4 + 2);
        W3 = __ldg(((const float4*)We) + c4 + 3);
    } else {
        W0 = W1 = W2 = W3 = z;
    }

    float4 rsum = z;   // readout accumulator (half 0 active lanes)

    while (true) {
        int b = 0;
        if (lane == 0) b = atomicAdd(&d_ctr[layer], 8);
        b = __shfl_sync(0xffffffffu, b, 0);
        if (b >= N_NODES) break;
        int bend = min(b + 8, N_NODES);

        for (int v = b; v < bend; v++) {
            float4 xr4 = active ? ((const float4*)d_xr)[v * 12 + L] : z;
            float den = 0.f;
            float4 acc = z;
            int beg = d_off[v], end = d_off[v + 1];
            int i = beg + half;

            // 2-edge unrolled main loop (edges i and i+2 for this half)
            for (; i + 2 < end; i += 4) {
                int u1 = __ldg(&d_srcs[i]);
                int u2 = __ldg(&d_srcs[i + 2]);
                float4 e1 = __ldg(&d_eas[i]);
                float4 e2 = __ldg(&d_eas[i + 2]);
                float4 x1 = active ? __ldg(((const float4*)d_xl) + u1 * 12 + L) : z;
                float4 x2 = active ? __ldg(((const float4*)d_xl) + u2 * 12 + L) : z;

                float4 m1, m2;
                m1.x = x1.x + xr4.x + e1.x * W0.x + e1.y * W0.y + e1.z * W0.z + e1.w * W0.w;
                m1.y = x1.y + xr4.y + e1.x * W1.x + e1.y * W1.y + e1.z * W1.z + e1.w * W1.w;
                m1.z = x1.z + xr4.z + e1.x * W2.x + e1.y * W2.y + e1.z * W2.z + e1.w * W2.w;
                m1.w = x1.w + xr4.w + e1.x * W3.x + e1.y * W3.y + e1.z * W3.z + e1.w * W3.w;
                m2.x = x2.x + xr4.x + e2.x * W0.x + e2.y * W0.y + e2.z * W0.z + e2.w * W0.w;
                m2.y = x2.y + xr4.y + e2.x * W1.x + e2.y * W1.y + e2.z * W1.z + e2.w * W1.w;
                m2.z = x2.z + xr4.z + e2.x * W2.x + e2.y * W2.y + e2.z * W2.z + e2.w * W2.w;
                m2.w = x2.w + xr4.w + e2.x * W3.x + e2.y * W3.y + e2.z * W3.z + e2.w * W3.w;

                float p1 = a4.x * fmaxf(m1.x, SLOPE * m1.x) + a4.y * fmaxf(m1.y, SLOPE * m1.y)
                         + a4.z * fmaxf(m1.z, SLOPE * m1.z) + a4.w * fmaxf(m1.w, SLOPE * m1.w);
                float p2 = a4.x * fmaxf(m2.x, SLOPE * m2.x) + a4.y * fmaxf(m2.y, SLOPE * m2.y)
                         + a4.z * fmaxf(m2.z, SLOPE * m2.z) + a4.w * fmaxf(m2.w, SLOPE * m2.w);
                p1 = redux_add_fix(p1, hmask);
                p2 = redux_add_fix(p2, hmask);
                float w1 = __expf(p1);
                float w2 = __expf(p2);
                den  += w1 + w2;
                acc.x += w1 * x1.x + w2 * x2.x;
                acc.y += w1 * x1.y + w2 * x2.y;
                acc.z += w1 * x1.z + w2 * x2.z;
                acc.w += w1 * x1.w + w2 * x2.w;
            }
            // remainder (at most one edge per half)
            for (; i < end; i += 2) {
                int u1 = __ldg(&d_srcs[i]);
                float4 e1 = __ldg(&d_eas[i]);
                float4 x1 = active ? __ldg(((const float4*)d_xl) + u1 * 12 + L) : z;
                float4 m1;
                m1.x = x1.x + xr4.x + e1.x * W0.x + e1.y * W0.y + e1.z * W0.z + e1.w * W0.w;
                m1.y = x1.y + xr4.y + e1.x * W1.x + e1.y * W1.y + e1.z * W1.z + e1.w * W1.w;
                m1.z = x1.z + xr4.z + e1.x * W2.x + e1.y * W2.y + e1.z * W2.z + e1.w * W2.w;
                m1.w = x1.w + xr4.w + e1.x * W3.x + e1.y * W3.y + e1.z * W3.z + e1.w * W3.w;
                float p1 = a4.x * fmaxf(m1.x, SLOPE * m1.x) + a4.y * fmaxf(m1.y, SLOPE * m1.y)
                         + a4.z * fmaxf(m1.z, SLOPE * m1.z) + a4.w * fmaxf(m1.w, SLOPE * m1.w);
                p1 = redux_add_fix(p1, hmask);
                float w1 = __expf(p1);
                den  += w1;
                acc.x += w1 * x1.x;
                acc.y += w1 * x1.y;
                acc.z += w1 * x1.z;
                acc.w += w1 * x1.w;
            }

            // reconverge warp, merge the two halves' sums (pairwise exchange)
            __syncwarp();
            den   += __shfl_xor_sync(0xffffffffu, den,   16);
            acc.x += __shfl_xor_sync(0xffffffffu, acc.x, 16);
            acc.y += __shfl_xor_sync(0xffffffffu, acc.y, 16);
            acc.z += __shfl_xor_sync(0xffffffffu, acc.z, 16);
            acc.w += __shfl_xor_sync(0xffffffffu, acc.w, 16);

            if (half == 0 && active) {
                float inv = 1.f / fmaxf(den, 1e-16f);
                float4 out;
                out.x = fmaxf(fmaf(acc.x, inv, b4.x), 0.f);
                out.y = fmaxf(fmaf(acc.y, inv, b4.y), 0.f);
                out.z = fmaxf(fmaf(acc.z, inv, b4.z), 0.f);
                out.w = fmaxf(fmaf(acc.w, inv, b4.w), 0.f);
                ((float4*)d_h)[v * 12 + L] = out;
                if (fuse_readout) {
                    rsum.x += out.x; rsum.y += out.y;
                    rsum.z += out.z; rsum.w += out.w;
                }
            }
        }
    }

    if (fuse_readout) {
        if (half == 0 && active) {
            int c4 = L * 4;
            atomicAdd(&sG[c4 + 0], rsum.x);
            atomicAdd(&sG[c4 + 1], rsum.y);
            atomicAdd(&sG[c4 + 2], rsum.z);
            atomicAdd(&sG[c4 + 3], rsum.w);
        }
        __syncthreads();
        if (t < AGG) atomicAdd(&d_g[t], sG[t]);
    }
}

// ---------------- MLP head + softmax ----------------
__global__ void k_mlp(const float* __restrict__ fc1w, const float* __restrict__ fc1b,
                      const float* __restrict__ fc2w, const float* __restrict__ fc2b,
                      float* __restrict__ out) {
    __shared__ float sg[AGG];
    __shared__ float sf[FC_H];
    __shared__ float sl[NC];
    int t = threadIdx.x;
    if (t < AGG) sg[t] = d_g[t];
    __syncthreads();
    if (t < FC_H) {
        float s = fc1b[t];
        #pragma unroll 8
        for (int k = 0; k < AGG; k++) s = fmaf(sg[k], fc1w[t * AGG + k], s);
        sf[t] = fmaxf(s, 0.f);
    }
    __syncthreads();
    if (t < NC) {
        float s = fc2b[t];
        for (int k = 0; k < FC_H; k++) s = fmaf(sf[k], fc2w[t * FC_H + k], s);
        sl[t] = s;
    }
    __syncthreads();
    if (t == 0) {
        float mx = sl[0];
        for (int i = 1; i < NC; i++) mx = fmaxf(mx, sl[i]);
        float sum = 0.f, ex[NC];
        for (int i = 0; i < NC; i++) { ex[i] = expf(sl[i] - mx); sum += ex[i]; }
        for (int i = 0; i < NC; i++) out[i] = ex[i] / sum;
    }
}

// ---------------- launch ----------------
extern "C" void kernel_launch(void* const* d_in, const int* in_sizes, int n_in,
                              void* d_out, int out_size) {
    const float* x   = (const float*)d_in[0];
    const int*   ei  = (const int*)d_in[1];
    const int*   src = ei;
    const int*   dst = ei + N_EDGES;
    const float* ea  = (const float*)d_in[2];

    const float *Wl[3], *bl[3], *Wr[3], *br[3], *We[3], *att[3], *bb[3];
    for (int l = 0; l < 3; l++) {
        int base = 3 + l * 7;
        Wl[l]  = (const float*)d_in[base + 0];
        bl[l]  = (const float*)d_in[base + 1];
        Wr[l]  = (const float*)d_in[base + 2];
        br[l]  = (const float*)d_in[base + 3];
        We[l]  = (const float*)d_in[base + 4];
        att[l] = (const float*)d_in[base + 5];
        bb[l]  = (const float*)d_in[base + 6];
    }
    const float* fc1w = (const float*)d_in[24];
    const float* fc1b = (const float*)d_in[25];
    const float* fc2w = (const float*)d_in[26];
    const float* fc2b = (const float*)d_in[27];
    float* out = (float*)d_out;

    k_zero   <<<(N_NODES + 255) / 256, 256>>>();
    k_count  <<<(N_EDGES + 255) / 256, 256>>>(dst);
    k_scan   <<<1, 1024>>>();
    k_scatter<<<(N_EDGES + 255) / 256, 256>>>(src, dst, (const float4*)ea);

    for (int l = 0; l < 3; l++) {
        int D = (l == 0) ? F_INDIM : AGG;
        k_gemm2<<<N_NODES / 80, 256>>>(x, (l > 0) ? 1 : 0, D, Wl[l], bl[l], Wr[l], br[l]);
        k_agg  <<<1184, 256>>>(We[l], att[l], bb[l], l, (l == 2) ? 1 : 0);
    }

    k_mlp<<<1, 192>>>(fc1w, fc1b, fc2w, fc2b, out);
}

// round 16
// speedup vs baseline: 1.0628x; 1.0628x over previous
#include <cuda_runtime.h>
#include <math.h>

#define N_NODES 100000
#define N_EDGES 1600000
#define F_INDIM 128
#define AGG 48
#define FC_H 192
#define NC 10
#define SLOPE 0.2f

// ---------------- scratch (static device globals; no allocation) ----------------
__device__ float  d_xl[N_NODES * AGG];
__device__ float  d_xr[N_NODES * AGG];
__device__ float  d_h [N_NODES * AGG];
__device__ float  d_g [AGG];
__device__ int    d_deg[N_NODES];
__device__ int    d_off[N_NODES + 1];
__device__ int    d_cur[N_NODES];
__device__ int    d_ctr[4];            // per-layer work-stealing counters
__device__ int    d_srcs[N_EDGES];     // src ids, CSR (dst-sorted) order
__device__ float4 d_eas[N_EDGES];      // edge attrs, CSR order

// ---------------- CSR build ----------------
__global__ void k_zero() {
    int i = blockIdx.x * blockDim.x + threadIdx.x;
    if (i < N_NODES) d_deg[i] = 0;
    if (i < AGG)     d_g[i] = 0.f;
    if (i < 4)       d_ctr[i] = 0;
}

__global__ void k_count(const int* __restrict__ dst) {
    int e = blockIdx.x * blockDim.x + threadIdx.x;
    if (e < N_EDGES) atomicAdd(&d_deg[dst[e]], 1);
}

// single-block exclusive scan, int4-vectorized (25 chunk iterations)
__global__ void k_scan() {
    __shared__ int wsum[32];
    __shared__ int carry;
    int t = threadIdx.x, lane = t & 31, w = t >> 5;
    if (t == 0) carry = 0;
    __syncthreads();
    for (int base = 0; base < N_NODES; base += 4096) {
        int idx = base + t * 4;
        int4 v4 = make_int4(0, 0, 0, 0);
        if (idx < N_NODES) v4 = *(const int4*)&d_deg[idx];   // N_NODES % 4 == 0
        int s = v4.x + v4.y + v4.z + v4.w;
        int x = s;
        #pragma unroll
        for (int o = 1; o < 32; o <<= 1) {
            int y = __shfl_up_sync(0xffffffffu, x, o);
            if (lane >= o) x += y;
        }
        if (lane == 31) wsum[w] = x;
        __syncthreads();
        if (w == 0) {
            int ss = wsum[lane];
            #pragma unroll
            for (int o = 1; o < 32; o <<= 1) {
                int y = __shfl_up_sync(0xffffffffu, ss, o);
                if (lane >= o) ss += y;
            }
            wsum[lane] = ss;
        }
        __syncthreads();
        int incl = x + (w > 0 ? wsum[w - 1] : 0) + carry;
        if (idx < N_NODES) {
            int o0 = incl - s;
            int o1 = o0 + v4.x;
            int o2 = o1 + v4.y;
            int o3 = o2 + v4.z;
            d_off[idx] = o0;     d_cur[idx] = o0;
            d_off[idx + 1] = o1; d_cur[idx + 1] = o1;
            d_off[idx + 2] = o2; d_cur[idx + 2] = o2;
            d_off[idx + 3] = o3; d_cur[idx + 3] = o3;
        }
        __syncthreads();
        if (t == 1023) carry = incl;
        __syncthreads();
    }
    if (t == 0) d_off[N_NODES] = carry;
}

// scatter edges into CSR order, pre-gathering src id and edge attr
__global__ void k_scatter(const int* __restrict__ src, const int* __restrict__ dst,
                          const float4* __restrict__ ea) {
    int e = blockIdx.x * blockDim.x + threadIdx.x;
    if (e < N_EDGES) {
        int p = atomicAdd(&d_cur[dst[e]], 1);
        d_srcs[p] = src[e];
        d_eas[p]  = ea[e];
    }
}

// ---------------- fused node-wise linears: xl = h@Wl.T+bl, xr = h@Wr.T+br ----------------
// Register-tiled: thread = 4 nodes x 4 channels. 240 active threads = 80 nodes/block.
__global__ void k_gemm2(const float* __restrict__ hin_ext, int use_h, int D,
                        const float* __restrict__ Wl, const float* __restrict__ bl,
                        const float* __restrict__ Wr, const float* __restrict__ br) {
    __shared__ float WsL[F_INDIM * AGG];  // transposed: Ws[k*48 + c]
    __shared__ float WsR[F_INDIM * AGG];
    const float* hin = use_h ? d_h : hin_ext;

    int t = threadIdx.x;
    int tot = D * AGG;
    for (int j = t; j < tot; j += blockDim.x) {
        int c = j / D, k = j % D;          // W row-major [AGG][D]
        WsL[k * AGG + c] = Wl[j];
        WsR[k * AGG + c] = Wr[j];
    }
    __syncthreads();
    if (t >= 240) return;

    int cg = t % 12;
    int grp = t / 12;
    int n0 = blockIdx.x * 80 + grp * 4;

    float4 bL = ((const float4*)bl)[cg];
    float4 bR = ((const float4*)br)[cg];
    float4 aL[4] = {bL, bL, bL, bL};
    float4 aR[4] = {bR, bR, bR, bR};

    const float* hp = hin + (size_t)n0 * D;

    for (int k = 0; k < D; k += 4) {
        float4 h4[4];
        #pragma unroll
        for (int nn = 0; nn < 4; nn++)
            h4[nn] = *(const float4*)(hp + nn * D + k);
        #pragma unroll
        for (int j = 0; j < 4; j++) {
            float4 wl = *(const float4*)&WsL[(k + j) * AGG + cg * 4];
            float4 wr = *(const float4*)&WsR[(k + j) * AGG + cg * 4];
            #pragma unroll
            for (int nn = 0; nn < 4; nn++) {
                float hv = (j == 0) ? h4[nn].x : (j == 1) ? h4[nn].y
                         : (j == 2) ? h4[nn].z : h4[nn].w;
                aL[nn].x = fmaf(hv, wl.x, aL[nn].x);
                aL[nn].y = fmaf(hv, wl.y, aL[nn].y);
                aL[nn].z = fmaf(hv, wl.z, aL[nn].z);
                aL[nn].w = fmaf(hv, wl.w, aL[nn].w);
                aR[nn].x = fmaf(hv, wr.x, aR[nn].x);
                aR[nn].y = fmaf(hv, wr.y, aR[nn].y);
                aR[nn].z = fmaf(hv, wr.z, aR[nn].z);
                aR[nn].w = fmaf(hv, wr.w, aR[nn].w);
            }
        }
    }
    #pragma unroll
    for (int nn = 0; nn < 4; nn++) {
        ((float4*)d_xl)[(n0 + nn) * 12 + cg] = aL[nn];
        ((float4*)d_xr)[(n0 + nn) * 12 + cg] = aR[nn];
    }
}

// ---------------- GATv2 aggregation: work-stealing warps, halves split edges ----------------
// R11 structure (676us) + SOFTWARE PIPELINING of the src/ea loads:
// the next iteration's (src, ea) pair is prefetched during the current iteration's
// compute, so the xl gather (which depends on src) issues at iteration start.
// Critical path per 2 edges: max(gather_lat, compute) instead of src_lat + gather_lat + compute.
// No running max (den = sum exp, acc = sum exp*xl). Remainder folded in via w2=0 predication
// (only the final iteration can be odd). HALF-mask shfls in loop; merge after syncwarp.
__global__ void k_agg(const float* __restrict__ We, const float* __restrict__ att,
                      const float* __restrict__ bias, int layer, int fuse_readout) {
    __shared__ float sG[AGG];
    int t = threadIdx.x;
    if (t < AGG) sG[t] = 0.f;
    __syncthreads();

    int lane = t & 31;
    int half = lane >> 4, L = lane & 15;
    unsigned hmask = 0xFFFFu << (half * 16);
    bool active = (L < 12);
    float4 z = make_float4(0, 0, 0, 0);

    float4 a4 = active ? __ldg(((const float4*)att) + L)  : z;
    float4 b4 = active ? __ldg(((const float4*)bias) + L) : z;
    float4 W0, W1, W2, W3;
    if (active) {
        int c4 = L * 4;
        W0 = __ldg(((const float4*)We) + c4 + 0);
        W1 = __ldg(((const float4*)We) + c4 + 1);
        W2 = __ldg(((const float4*)We) + c4 + 2);
        W3 = __ldg(((const float4*)We) + c4 + 3);
    } else {
        W0 = W1 = W2 = W3 = z;
    }

    float4 rsum = z;   // readout accumulator (half 0 active lanes)

    while (true) {
        int b = 0;
        if (lane == 0) b = atomicAdd(&d_ctr[layer], 8);
        b = __shfl_sync(0xffffffffu, b, 0);
        if (b >= N_NODES) break;
        int bend = min(b + 8, N_NODES);

        for (int v = b; v < bend; v++) {
            float4 xr4 = active ? ((const float4*)d_xr)[v * 12 + L] : z;
            float den = 0.f;
            float4 acc = z;
            int beg = d_off[v], end = d_off[v + 1];

            int i = beg + half;
            bool v1 = i < end, v2 = (i + 2) < end;
            int u1 = 0, u2 = 0;
            float4 e1 = z, e2 = z;
            if (v1) { u1 = __ldg(&d_srcs[i]);     e1 = __ldg(&d_eas[i]); }
            if (v2) { u2 = __ldg(&d_srcs[i + 2]); e2 = __ldg(&d_eas[i + 2]); }

            while (v1) {
                // gathers for current pair (u1/u2 already resolved)
                float4 x1 = active          ? __ldg(((const float4*)d_xl) + u1 * 12 + L) : z;
                float4 x2 = (active && v2)  ? __ldg(((const float4*)d_xl) + u2 * 12 + L) : z;

                // prefetch next pair's indices/attrs
                int ni = i + 4;
                bool nv1 = ni < end, nv2 = (ni + 2) < end;
                int pu1 = 0, pu2 = 0;
                float4 pe1 = z, pe2 = z;
                if (nv1) { pu1 = __ldg(&d_srcs[ni]);     pe1 = __ldg(&d_eas[ni]); }
                if (nv2) { pu2 = __ldg(&d_srcs[ni + 2]); pe2 = __ldg(&d_eas[ni + 2]); }

                float4 m1, m2;
                m1.x = x1.x + xr4.x + e1.x * W0.x + e1.y * W0.y + e1.z * W0.z + e1.w * W0.w;
                m1.y = x1.y + xr4.y + e1.x * W1.x + e1.y * W1.y + e1.z * W1.z + e1.w * W1.w;
                m1.z = x1.z + xr4.z + e1.x * W2.x + e1.y * W2.y + e1.z * W2.z + e1.w * W2.w;
                m1.w = x1.w + xr4.w + e1.x * W3.x + e1.y * W3.y + e1.z * W3.z + e1.w * W3.w;
                m2.x = x2.x + xr4.x + e2.x * W0.x + e2.y * W0.y + e2.z * W0.z + e2.w * W0.w;
                m2.y = x2.y + xr4.y + e2.x * W1.x + e2.y * W1.y + e2.z * W1.z + e2.w * W1.w;
                m2.z = x2.z + xr4.z + e2.x * W2.x + e2.y * W2.y + e2.z * W2.z + e2.w * W2.w;
                m2.w = x2.w + xr4.w + e2.x * W3.x + e2.y * W3.y + e2.z * W3.z + e2.w * W3.w;

                float p1 = a4.x * fmaxf(m1.x, SLOPE * m1.x) + a4.y * fmaxf(m1.y, SLOPE * m1.y)
                         + a4.z * fmaxf(m1.z, SLOPE * m1.z) + a4.w * fmaxf(m1.w, SLOPE * m1.w);
                float p2 = a4.x * fmaxf(m2.x, SLOPE * m2.x) + a4.y * fmaxf(m2.y, SLOPE * m2.y)
                         + a4.z * fmaxf(m2.z, SLOPE * m2.z) + a4.w * fmaxf(m2.w, SLOPE * m2.w);
                #pragma unroll
                for (int o = 8; o > 0; o >>= 1) {
                    p1 += __shfl_xor_sync(hmask, p1, o);
                    p2 += __shfl_xor_sync(hmask, p2, o);
                }
                float w1 = __expf(p1);                  // v1 guaranteed true here
                float w2 = v2 ? __expf(p2) : 0.f;       // uniform within half
                den  += w1 + w2;
                acc.x += w1 * x1.x + w2 * x2.x;
                acc.y += w1 * x1.y + w2 * x2.y;
                acc.z += w1 * x1.z + w2 * x2.z;
                acc.w += w1 * x1.w + w2 * x2.w;

                i = ni; v1 = nv1; v2 = nv2;
                u1 = pu1; u2 = pu2; e1 = pe1; e2 = pe2;
            }

            // reconverge warp, merge the two halves' sums (pairwise exchange)
            __syncwarp();
            den   += __shfl_xor_sync(0xffffffffu, den,   16);
            acc.x += __shfl_xor_sync(0xffffffffu, acc.x, 16);
            acc.y += __shfl_xor_sync(0xffffffffu, acc.y, 16);
            acc.z += __shfl_xor_sync(0xffffffffu, acc.z, 16);
            acc.w += __shfl_xor_sync(0xffffffffu, acc.w, 16);

            if (half == 0 && active) {
                float inv = 1.f / fmaxf(den, 1e-16f);
                float4 out;
                out.x = fmaxf(fmaf(acc.x, inv, b4.x), 0.f);
                out.y = fmaxf(fmaf(acc.y, inv, b4.y), 0.f);
                out.z = fmaxf(fmaf(acc.z, inv, b4.z), 0.f);
                out.w = fmaxf(fmaf(acc.w, inv, b4.w), 0.f);
                ((float4*)d_h)[v * 12 + L] = out;
                if (fuse_readout) {
                    rsum.x += out.x; rsum.y += out.y;
                    rsum.z += out.z; rsum.w += out.w;
                }
            }
        }
    }

    if (fuse_readout) {
        if ((lane >> 4) == 0 && active) {
            int c4 = L * 4;
            atomicAdd(&sG[c4 + 0], rsum.x);
            atomicAdd(&sG[c4 + 1], rsum.y);
            atomicAdd(&sG[c4 + 2], rsum.z);
            atomicAdd(&sG[c4 + 3], rsum.w);
        }
        __syncthreads();
        if (t < AGG) atomicAdd(&d_g[t], sG[t]);
    }
}

// ---------------- MLP head + softmax ----------------
__global__ void k_mlp(const float* __restrict__ fc1w, const float* __restrict__ fc1b,
                      const float* __restrict__ fc2w, const float* __restrict__ fc2b,
                      float* __restrict__ out) {
    __shared__ float sg[AGG];
    __shared__ float sf[FC_H];
    __shared__ float sl[NC];
    int t = threadIdx.x;
    if (t < AGG) sg[t] = d_g[t];
    __syncthreads();
    if (t < FC_H) {
        float s = fc1b[t];
        #pragma unroll 8
        for (int k = 0; k < AGG; k++) s = fmaf(sg[k], fc1w[t * AGG + k], s);
        sf[t] = fmaxf(s, 0.f);
    }
    __syncthreads();
    if (t < NC) {
        float s = fc2b[t];
        for (int k = 0; k < FC_H; k++) s = fmaf(sf[k], fc2w[t * FC_H + k], s);
        sl[t] = s;
    }
    __syncthreads();
    if (t == 0) {
        float mx = sl[0];
        for (int i = 1; i < NC; i++) mx = fmaxf(mx, sl[i]);
        float sum = 0.f, ex[NC];
        for (int i = 0; i < NC; i++) { ex[i] = expf(sl[i] - mx); sum += ex[i]; }
        for (int i = 0; i < NC; i++) out[i] = ex[i] / sum;
    }
}

// ---------------- launch ----------------
extern "C" void kernel_launch(void* const* d_in, const int* in_sizes, int n_in,
                              void* d_out, int out_size) {
    const float* x   = (const float*)d_in[0];
    const int*   ei  = (const int*)d_in[1];
    const int*   src = ei;
    const int*   dst = ei + N_EDGES;
    const float* ea  = (const float*)d_in[2];

    const float *Wl[3], *bl[3], *Wr[3], *br[3], *We[3], *att[3], *bb[3];
    for (int l = 0; l < 3; l++) {
        int base = 3 + l * 7;
        Wl[l]  = (const float*)d_in[base + 0];
        bl[l]  = (const float*)d_in[base + 1];
        Wr[l]  = (const float*)d_in[base + 2];
        br[l]  = (const float*)d_in[base + 3];
        We[l]  = (const float*)d_in[base + 4];
        att[l] = (const float*)d_in[base + 5];
        bb[l]  = (const float*)d_in[base + 6];
    }
    const float* fc1w = (const float*)d_in[24];
    const float* fc1b = (const float*)d_in[25];
    const float* fc2w = (const float*)d_in[26];
    const float* fc2b = (const float*)d_in[27];
    float* out = (float*)d_out;

    k_zero   <<<(N_NODES + 255) / 256, 256>>>();
    k_count  <<<(N_EDGES + 255) / 256, 256>>>(dst);
    k_scan   <<<1, 1024>>>();
    k_scatter<<<(N_EDGES + 255) / 256, 256>>>(src, dst, (const float4*)ea);

    for (int l = 0; l < 3; l++) {
        int D = (l == 0) ? F_INDIM : AGG;
        k_gemm2<<<N_NODES / 80, 256>>>(x, (l > 0) ? 1 : 0, D, Wl[l], bl[l], Wr[l], br[l]);
        k_agg  <<<1184, 256>>>(We[l], att[l], bb[l], l, (l == 2) ? 1 : 0);
    }

    k_mlp<<<1, 192>>>(fc1w, fc1b, fc2w, fc2b, out);
}

// round 17
// speedup vs baseline: 1.0990x; 1.0341x over previous
#include <cuda_runtime.h>
#include <math.h>

#define N_NODES 100000
#define N_EDGES 1600000
#define F_INDIM 128
#define AGG 48
#define FC_H 192
#define NC 10
#define SLOPE 0.2f
#define SCAN_CHUNK 4096
#define SCAN_BLOCKS ((N_NODES + SCAN_CHUNK - 1) / SCAN_CHUNK)   // 25

// ---------------- scratch (static device globals; no allocation) ----------------
__device__ float  d_xl[N_NODES * AGG];
__device__ float  d_xr[N_NODES * AGG];
__device__ float  d_h [N_NODES * AGG];
__device__ float  d_g [AGG];
__device__ int    d_deg[N_NODES];
__device__ int    d_off[N_NODES + 1];
__device__ int    d_cur[N_NODES];
__device__ int    d_ctr[4];            // per-layer work-stealing counters
__device__ int    d_bsum[SCAN_BLOCKS];
__device__ int    d_boff[SCAN_BLOCKS];
__device__ int    d_srcs[N_EDGES];     // src ids, CSR (dst-sorted) order
__device__ float4 d_eas[N_EDGES];      // edge attrs, CSR order

// ---------------- CSR build ----------------
__global__ void k_zero() {
    int i = blockIdx.x * blockDim.x + threadIdx.x;
    if (i < N_NODES) d_deg[i] = 0;
    if (i < AGG)     d_g[i] = 0.f;
    if (i < 4)       d_ctr[i] = 0;
}

__global__ void k_count(const int* __restrict__ dst) {
    int e = blockIdx.x * blockDim.x + threadIdx.x;
    if (e < N_EDGES) atomicAdd(&d_deg[dst[e]], 1);
}

// parallel scan stage A: per-block local exclusive scan + block sum
__global__ void k_scan_a() {
    __shared__ int wsum[32];
    int b = blockIdx.x, t = threadIdx.x, lane = t & 31, w = t >> 5;
    int idx = b * SCAN_CHUNK + t * 4;
    int4 v4 = make_int4(0, 0, 0, 0);
    if (idx < N_NODES) v4 = *(const int4*)&d_deg[idx];   // N_NODES % 4 == 0
    int s = v4.x + v4.y + v4.z + v4.w;
    int x = s;
    #pragma unroll
    for (int o = 1; o < 32; o <<= 1) {
        int y = __shfl_up_sync(0xffffffffu, x, o);
        if (lane >= o) x += y;
    }
    if (lane == 31) wsum[w] = x;
    __syncthreads();
    if (w == 0) {
        int ss = wsum[lane];
        #pragma unroll
        for (int o = 1; o < 32; o <<= 1) {
            int y = __shfl_up_sync(0xffffffffu, ss, o);
            if (lane >= o) ss += y;
        }
        wsum[lane] = ss;
    }
    __syncthreads();
    int incl = x + (w > 0 ? wsum[w - 1] : 0);
    if (idx < N_NODES) {
        int o0 = incl - s;
        d_off[idx]     = o0;
        d_off[idx + 1] = o0 + v4.x;
        d_off[idx + 2] = o0 + v4.x + v4.y;
        d_off[idx + 3] = o0 + v4.x + v4.y + v4.z;
    }
    if (t == 1023) d_bsum[b] = incl;
}

// stage B: exclusive scan of the 25 block sums (single warp)
__global__ void k_scan_b() {
    int t = threadIdx.x;
    int v = (t < SCAN_BLOCKS) ? d_bsum[t] : 0;
    int x = v;
    #pragma unroll
    for (int o = 1; o < 32; o <<= 1) {
        int y = __shfl_up_sync(0xffffffffu, x, o);
        if (t >= o) x += y;
    }
    if (t < SCAN_BLOCKS) d_boff[t] = x - v;
    if (t == 0) d_off[N_NODES] = N_EDGES;   // total is a constant
}

// stage C: add block offsets, fill d_cur
__global__ void k_scan_c() {
    int b = blockIdx.x, t = threadIdx.x;
    int add = d_boff[b];
    int idx = b * SCAN_CHUNK + t * 4;
    if (idx < N_NODES) {
        int4 o4 = *(const int4*)&d_off[idx];
        o4.x += add; o4.y += add; o4.z += add; o4.w += add;
        *(int4*)&d_off[idx] = o4;
        *(int4*)&d_cur[idx] = o4;
    }
}

// scatter edges into CSR order, pre-gathering src id and edge attr
__global__ void k_scatter(const int* __restrict__ src, const int* __restrict__ dst,
                          const float4* __restrict__ ea) {
    int e = blockIdx.x * blockDim.x + threadIdx.x;
    if (e < N_EDGES) {
        int p = atomicAdd(&d_cur[dst[e]], 1);
        d_srcs[p] = src[e];
        d_eas[p]  = ea[e];
    }
}

// ---------------- fused node-wise linears: xl = h@Wl.T+bl, xr = h@Wr.T+br ----------------
// Register-tiled: thread = 4 nodes x 4 channels. 240 active threads = 80 nodes/block.
__global__ void k_gemm2(const float* __restrict__ hin_ext, int use_h, int D,
                        const float* __restrict__ Wl, const float* __restrict__ bl,
                        const float* __restrict__ Wr, const float* __restrict__ br) {
    __shared__ float WsL[F_INDIM * AGG];  // transposed: Ws[k*48 + c]
    __shared__ float WsR[F_INDIM * AGG];
    const float* hin = use_h ? d_h : hin_ext;

    int t = threadIdx.x;
    int tot = D * AGG;
    for (int j = t; j < tot; j += blockDim.x) {
        int c = j / D, k = j % D;          // W row-major [AGG][D]
        WsL[k * AGG + c] = Wl[j];
        WsR[k * AGG + c] = Wr[j];
    }
    __syncthreads();
    if (t >= 240) return;

    int cg = t % 12;
    int grp = t / 12;
    int n0 = blockIdx.x * 80 + grp * 4;

    float4 bL = ((const float4*)bl)[cg];
    float4 bR = ((const float4*)br)[cg];
    float4 aL[4] = {bL, bL, bL, bL};
    float4 aR[4] = {bR, bR, bR, bR};

    const float* hp = hin + (size_t)n0 * D;

    for (int k = 0; k < D; k += 4) {
        float4 h4[4];
        #pragma unroll
        for (int nn = 0; nn < 4; nn++)
            h4[nn] = *(const float4*)(hp + nn * D + k);
        #pragma unroll
        for (int j = 0; j < 4; j++) {
            float4 wl = *(const float4*)&WsL[(k + j) * AGG + cg * 4];
            float4 wr = *(const float4*)&WsR[(k + j) * AGG + cg * 4];
            #pragma unroll
            for (int nn = 0; nn < 4; nn++) {
                float hv = (j == 0) ? h4[nn].x : (j == 1) ? h4[nn].y
                         : (j == 2) ? h4[nn].z : h4[nn].w;
                aL[nn].x = fmaf(hv, wl.x, aL[nn].x);
                aL[nn].y = fmaf(hv, wl.y, aL[nn].y);
                aL[nn].z = fmaf(hv, wl.z, aL[nn].z);
                aL[nn].w = fmaf(hv, wl.w, aL[nn].w);
                aR[nn].x = fmaf(hv, wr.x, aR[nn].x);
                aR[nn].y = fmaf(hv, wr.y, aR[nn].y);
                aR[nn].z = fmaf(hv, wr.z, aR[nn].z);
                aR[nn].w = fmaf(hv, wr.w, aR[nn].w);
            }
        }
    }
    #pragma unroll
    for (int nn = 0; nn < 4; nn++) {
        ((float4*)d_xl)[(n0 + nn) * 12 + cg] = aL[nn];
        ((float4*)d_xr)[(n0 + nn) * 12 + cg] = aR[nn];
    }
}

// ---------------- GATv2 aggregation: work-stealing warps, half-warp per node ----------------
// Each warp steals batches of 16 nodes (100000 % 16 == 0 -> no clipping). The two
// 16-lane halves own DISJOINT nodes (v = b + 2k + half): inner loop identical to the
// proven R11 version, but edges stride 1, and there is NO cross-half merge/syncwarp.
// No running max (den = sum exp, acc = sum exp*xl). HALF-mask shfls only.
__global__ void k_agg(const float* __restrict__ We, const float* __restrict__ att,
                      const float* __restrict__ bias, int layer, int fuse_readout) {
    __shared__ float sG[AGG];
    int t = threadIdx.x;
    if (t < AGG) sG[t] = 0.f;
    __syncthreads();

    int lane = t & 31;
    int half = lane >> 4, L = lane & 15;
    unsigned hmask = 0xFFFFu << (half * 16);
    bool active = (L < 12);
    float4 z = make_float4(0, 0, 0, 0);

    float4 a4 = active ? __ldg(((const float4*)att) + L)  : z;
    float4 b4 = active ? __ldg(((const float4*)bias) + L) : z;
    float4 W0, W1, W2, W3;
    if (active) {
        int c4 = L * 4;
        W0 = __ldg(((const float4*)We) + c4 + 0);
        W1 = __ldg(((const float4*)We) + c4 + 1);
        W2 = __ldg(((const float4*)We) + c4 + 2);
        W3 = __ldg(((const float4*)We) + c4 + 3);
    } else {
        W0 = W1 = W2 = W3 = z;
    }

    float4 rsum = z;   // readout accumulator (active lanes of both halves)

    while (true) {
        int b = 0;
        if (lane == 0) b = atomicAdd(&d_ctr[layer], 16);
        b = __shfl_sync(0xffffffffu, b, 0);
        if (b >= N_NODES) break;

        #pragma unroll 1
        for (int k = 0; k < 8; k++) {
            int v = b + k * 2 + half;          // uniform within each half
            float4 xr4 = active ? ((const float4*)d_xr)[v * 12 + L] : z;
            float den = 0.f;
            float4 acc = z;
            int beg = d_off[v], end = d_off[v + 1];
            int i = beg;

            // 2-edge unrolled main loop (edges i and i+1)
            for (; i + 1 < end; i += 2) {
                int u1 = __ldg(&d_srcs[i]);
                int u2 = __ldg(&d_srcs[i + 1]);
                float4 e1 = __ldg(&d_eas[i]);
                float4 e2 = __ldg(&d_eas[i + 1]);
                float4 x1 = active ? __ldg(((const float4*)d_xl) + u1 * 12 + L) : z;
                float4 x2 = active ? __ldg(((const float4*)d_xl) + u2 * 12 + L) : z;

                float4 m1, m2;
                m1.x = x1.x + xr4.x + e1.x * W0.x + e1.y * W0.y + e1.z * W0.z + e1.w * W0.w;
                m1.y = x1.y + xr4.y + e1.x * W1.x + e1.y * W1.y + e1.z * W1.z + e1.w * W1.w;
                m1.z = x1.z + xr4.z + e1.x * W2.x + e1.y * W2.y + e1.z * W2.z + e1.w * W2.w;
                m1.w = x1.w + xr4.w + e1.x * W3.x + e1.y * W3.y + e1.z * W3.z + e1.w * W3.w;
                m2.x = x2.x + xr4.x + e2.x * W0.x + e2.y * W0.y + e2.z * W0.z + e2.w * W0.w;
                m2.y = x2.y + xr4.y + e2.x * W1.x + e2.y * W1.y + e2.z * W1.z + e2.w * W1.w;
                m2.z = x2.z + xr4.z + e2.x * W2.x + e2.y * W2.y + e2.z * W2.z + e2.w * W2.w;
                m2.w = x2.w + xr4.w + e2.x * W3.x + e2.y * W3.y + e2.z * W3.z + e2.w * W3.w;

                float p1 = a4.x * fmaxf(m1.x, SLOPE * m1.x) + a4.y * fmaxf(m1.y, SLOPE * m1.y)
                         + a4.z * fmaxf(m1.z, SLOPE * m1.z) + a4.w * fmaxf(m1.w, SLOPE * m1.w);
                float p2 = a4.x * fmaxf(m2.x, SLOPE * m2.x) + a4.y * fmaxf(m2.y, SLOPE * m2.y)
                         + a4.z * fmaxf(m2.z, SLOPE * m2.z) + a4.w * fmaxf(m2.w, SLOPE * m2.w);
                #pragma unroll
                for (int o = 8; o > 0; o >>= 1) {
                    p1 += __shfl_xor_sync(hmask, p1, o);
                    p2 += __shfl_xor_sync(hmask, p2, o);
                }
                float w1 = __expf(p1);
                float w2 = __expf(p2);
                den  += w1 + w2;
                acc.x += w1 * x1.x + w2 * x2.x;
                acc.y += w1 * x1.y + w2 * x2.y;
                acc.z += w1 * x1.z + w2 * x2.z;
                acc.w += w1 * x1.w + w2 * x2.w;
            }
            // remainder (at most one edge)
            for (; i < end; i++) {
                int u1 = __ldg(&d_srcs[i]);
                float4 e1 = __ldg(&d_eas[i]);
                float4 x1 = active ? __ldg(((const float4*)d_xl) + u1 * 12 + L) : z;
                float4 m1;
                m1.x = x1.x + xr4.x + e1.x * W0.x + e1.y * W0.y + e1.z * W0.z + e1.w * W0.w;
                m1.y = x1.y + xr4.y + e1.x * W1.x + e1.y * W1.y + e1.z * W1.z + e1.w * W1.w;
                m1.z = x1.z + xr4.z + e1.x * W2.x + e1.y * W2.y + e1.z * W2.z + e1.w * W2.w;
                m1.w = x1.w + xr4.w + e1.x * W3.x + e1.y * W3.y + e1.z * W3.z + e1.w * W3.w;
                float p1 = a4.x * fmaxf(m1.x, SLOPE * m1.x) + a4.y * fmaxf(m1.y, SLOPE * m1.y)
                         + a4.z * fmaxf(m1.z, SLOPE * m1.z) + a4.w * fmaxf(m1.w, SLOPE * m1.w);
                #pragma unroll
                for (int o = 8; o > 0; o >>= 1)
                    p1 += __shfl_xor_sync(hmask, p1, o);
                float w1 = __expf(p1);
                den  += w1;
                acc.x += w1 * x1.x;
                acc.y += w1 * x1.y;
                acc.z += w1 * x1.z;
                acc.w += w1 * x1.w;
            }

            if (active) {
                float inv = 1.f / fmaxf(den, 1e-16f);
                float4 out;
                out.x = fmaxf(fmaf(acc.x, inv, b4.x), 0.f);
                out.y = fmaxf(fmaf(acc.y, inv, b4.y), 0.f);
                out.z = fmaxf(fmaf(acc.z, inv, b4.z), 0.f);
                out.w = fmaxf(fmaf(acc.w, inv, b4.w), 0.f);
                ((float4*)d_h)[v * 12 + L] = out;
                if (fuse_readout) {
                    rsum.x += out.x; rsum.y += out.y;
                    rsum.z += out.z; rsum.w += out.w;
                }
            }
        }
    }

    if (fuse_readout) {
        if (active) {
            int c4 = L * 4;
            atomicAdd(&sG[c4 + 0], rsum.x);
            atomicAdd(&sG[c4 + 1], rsum.y);
            atomicAdd(&sG[c4 + 2], rsum.z);
            atomicAdd(&sG[c4 + 3], rsum.w);
        }
        __syncthreads();
        if (t < AGG) atomicAdd(&d_g[t], sG[t]);
    }
}

// ---------------- MLP head + softmax ----------------
__global__ void k_mlp(const float* __restrict__ fc1w, const float* __restrict__ fc1b,
                      const float* __restrict__ fc2w, const float* __restrict__ fc2b,
                      float* __restrict__ out) {
    __shared__ float sg[AGG];
    __shared__ float sf[FC_H];
    __shared__ float sl[NC];
    int t = threadIdx.x;
    if (t < AGG) sg[t] = d_g[t];
    __syncthreads();
    if (t < FC_H) {
        float s = fc1b[t];
        #pragma unroll 8
        for (int k = 0; k < AGG; k++) s = fmaf(sg[k], fc1w[t * AGG + k], s);
        sf[t] = fmaxf(s, 0.f);
    }
    __syncthreads();
    if (t < NC) {
        float s = fc2b[t];
        for (int k = 0; k < FC_H; k++) s = fmaf(sf[k], fc2w[t * FC_H + k], s);
        sl[t] = s;
    }
    __syncthreads();
    if (t == 0) {
        float mx = sl[0];
        for (int i = 1; i < NC; i++) mx = fmaxf(mx, sl[i]);
        float sum = 0.f, ex[NC];
        for (int i = 0; i < NC; i++) { ex[i] = expf(sl[i] - mx); sum += ex[i]; }
        for (int i = 0; i < NC; i++) out[i] = ex[i] / sum;
    }
}

// ---------------- launch ----------------
extern "C" void kernel_launch(void* const* d_in, const int* in_sizes, int n_in,
                              void* d_out, int out_size) {
    const float* x   = (const float*)d_in[0];
    const int*   ei  = (const int*)d_in[1];
    const int*   src = ei;
    const int*   dst = ei + N_EDGES;
    const float* ea  = (const float*)d_in[2];

    const float *Wl[3], *bl[3], *Wr[3], *br[3], *We[3], *att[3], *bb[3];
    for (int l = 0; l < 3; l++) {
        int base = 3 + l * 7;
        Wl[l]  = (const float*)d_in[base + 0];
        bl[l]  = (const float*)d_in[base + 1];
        Wr[l]  = (const float*)d_in[base + 2];
        br[l]  = (const float*)d_in[base + 3];
        We[l]  = (const float*)d_in[base + 4];
        att[l] = (const float*)d_in[base + 5];
        bb[l]  = (const float*)d_in[base + 6];
    }
    const float* fc1w = (const float*)d_in[24];
    const float* fc1b = (const float*)d_in[25];
    const float* fc2w = (const float*)d_in[26];
    const float* fc2b = (const float*)d_in[27];
    float* out = (float*)d_out;

    k_zero   <<<(N_NODES + 255) / 256, 256>>>();
    k_count  <<<(N_EDGES + 255) / 256, 256>>>(dst);
    k_scan_a <<<SCAN_BLOCKS, 1024>>>();
    k_scan_b <<<1, 32>>>();
    k_scan_c <<<SCAN_BLOCKS, 1024>>>();
    k_scatter<<<(N_EDGES + 255) / 256, 256>>>(src, dst, (const float4*)ea);

    for (int l = 0; l < 3; l++) {
        int D = (l == 0) ? F_INDIM : AGG;
        k_gemm2<<<N_NODES / 80, 256>>>(x, (l > 0) ? 1 : 0, D, Wl[l], bl[l], Wr[l], br[l]);
        k_agg  <<<1184, 256>>>(We[l], att[l], bb[l], l, (l == 2) ? 1 : 0);
    }

    k_mlp<<<1, 192>>>(fc1w, fc1b, fc2w, fc2b, out);
}